// round 15
// baseline (speedup 1.0000x reference)
#include <cuda_runtime.h>
#include <cuda_fp16.h>
#include <cstdint>

// ---------------- problem constants ----------------
#define D_DIM 3072
#define N_DIM 8192
#define B_DIM 2

#define TM 128            // CTA M tile (d)
#define TN 128            // CTA N tile (n)
#define TK 64             // K tile (halves) = 128B per row
#define STAGES 3
#define NK (N_DIM / TK)   // 128 k iterations
#define MT (D_DIM / TM)   // 24
#define NT (N_DIM / TN)   // 64

// per-batch-half tiling: 1536 tiles = 1520 main (5 exact waves of 304) + 16 split-K tiles
#define TILES_H     (MT * NT)          // 1536
#define MAIN_H      1520
#define REM_H       (TILES_H - MAIN_H) // 16
#define KSPLIT      8
#define NK_PART     (NK / KSPLIT)      // 16
#define REM_CTAS_H  (REM_H * KSPLIT)   // 128
#define GRID_H      (MAIN_H + REM_CTAS_H) // 1648

#define ROWH 72                           // padded row (halves): conflict-free ldmatrix
#define TILE_H (128 * ROWH)               // 9216 halves per 128-row tile
#define STAGE_H (2 * TILE_H)              // A + B per stage = 36864 B
#define SMEM_BYTES (STAGES * STAGE_H * 2) // 110592 B -> 2 CTAs/SM

// cvt grid split: blocks < CVT_X_BLOCKS sweep x-half, rest sweep adj-half (balanced by elems)
#define CVT_BLOCKS   6080
#define CVT_X_BLOCKS 1664
#define CVT_THREADS  128   // small CTAs: 32 regs, 0 smem -> co-resident with GEMM CTAs

// fp16 scratch copies of the inputs (zero-init .bss; no runtime allocation)
__device__ __half g_xh[(size_t)B_DIM * D_DIM * N_DIM];
__device__ __half g_adjh[(size_t)B_DIM * N_DIM * N_DIM];
// split-K partials (reused per half; halves serialized by graph edges) + per-half counters
__device__ float g_part[(size_t)REM_H * KSPLIT * TM * TN];
__device__ int   g_cnt[B_DIM * REM_H];

// ---------------- PTX helpers ----------------
__device__ __forceinline__ uint32_t smem_u32(const void* p) {
    uint32_t a;
    asm("{ .reg .u64 t; cvta.to.shared.u64 t, %1; cvt.u32.u64 %0, t; }" : "=r"(a) : "l"(p));
    return a;
}
__device__ __forceinline__ void cp_async16(uint32_t saddr, const void* gaddr) {
    asm volatile("cp.async.cg.shared.global [%0], [%1], 16;" :: "r"(saddr), "l"(gaddr) : "memory");
}
#define CP_COMMIT() asm volatile("cp.async.commit_group;" ::: "memory")
#define CP_WAIT(n)  asm volatile("cp.async.wait_group %0;" :: "n"(n) : "memory")

__device__ __forceinline__ void ldmatrix_x4(uint32_t* r, uint32_t addr) {
    asm volatile("ldmatrix.sync.aligned.m8n8.x4.shared.b16 {%0,%1,%2,%3}, [%4];"
        : "=r"(r[0]), "=r"(r[1]), "=r"(r[2]), "=r"(r[3]) : "r"(addr));
}
__device__ __forceinline__ void mma_f16(float& c0, float& c1, float& c2, float& c3,
                                        uint32_t a0, uint32_t a1, uint32_t a2, uint32_t a3,
                                        uint32_t b0, uint32_t b1) {
    asm volatile(
        "mma.sync.aligned.m16n8k16.row.col.f32.f16.f16.f32 "
        "{%0,%1,%2,%3}, {%4,%5,%6,%7}, {%8,%9}, {%0,%1,%2,%3};"
        : "+f"(c0), "+f"(c1), "+f"(c2), "+f"(c3)
        : "r"(a0), "r"(a1), "r"(a2), "r"(a3), "r"(b0), "r"(b1));
}
__device__ __forceinline__ uint32_t pack_h2(float lo, float hi) {
    uint32_t u;
    asm("cvt.rn.f16x2.f32 %0, %1, %2;" : "=r"(u) : "f"(hi), "f"(lo));
    return u;
}

// ---------------- prepass: fp32 -> fp16 for ONE batch half ----------------
__global__ void __launch_bounds__(CVT_THREADS)
cvt_f2h_half_kernel(const float* __restrict__ x, __half* __restrict__ xh, size_t nx,
                    const float* __restrict__ adj, __half* __restrict__ adjh, size_t na,
                    int do_reset)
{
    // cvt_b0 resets BOTH halves' rem counters (stream-ordered before both GEMMs)
    if (do_reset && blockIdx.x == 0 && threadIdx.x < B_DIM * REM_H)
        g_cnt[threadIdx.x] = 0;

    const float* src;
    __half* dst;
    size_t n8, idx, stride;
    if (blockIdx.x < CVT_X_BLOCKS) {
        src = x;   dst = xh;   n8 = nx / 8;
        idx = (size_t)blockIdx.x * CVT_THREADS + threadIdx.x;
        stride = (size_t)CVT_X_BLOCKS * CVT_THREADS;
    } else {
        src = adj; dst = adjh; n8 = na / 8;
        idx = (size_t)(blockIdx.x - CVT_X_BLOCKS) * CVT_THREADS + threadIdx.x;
        stride = (size_t)(CVT_BLOCKS - CVT_X_BLOCKS) * CVT_THREADS;
    }
    for (; idx < n8; idx += stride) {
        const size_t i = idx * 8;
        float4 f0 = *reinterpret_cast<const float4*>(src + i);
        float4 f1 = *reinterpret_cast<const float4*>(src + i + 4);
        uint4 v;
        v.x = pack_h2(f0.x, f0.y);
        v.y = pack_h2(f0.z, f0.w);
        v.z = pack_h2(f1.x, f1.y);
        v.w = pack_h2(f1.z, f1.w);
        *reinterpret_cast<uint4*>(dst + i) = v;
    }
}

// ---------------- shared GEMM body (proven R10/R13 version) ----------------
struct GemmCtx {
    uint32_t sA_st, sB_st, aOff, bOff, sbase;
    const __half* gA;
    const __half* gB;
};

__device__ __forceinline__ void gemm_tile(const GemmCtx& cx, int kbeg, int kend,
                                          float (&acc)[4][8][4])
{
    const uint32_t sbase = cx.sbase;
    // prologue
    #pragma unroll
    for (int s = 0; s < STAGES - 1; s++) {
        const size_t k0 = (size_t)(kbeg + s) * TK;
        #pragma unroll
        for (int i = 0; i < 8; i++) {
            cp_async16(cx.sA_st + (uint32_t)(s * STAGE_H + i * 16 * ROWH) * 2, cx.gA + k0 + (size_t)i * 16 * N_DIM);
            cp_async16(cx.sB_st + (uint32_t)(s * STAGE_H + i * 16 * ROWH) * 2, cx.gB + k0 + (size_t)i * 16 * N_DIM);
        }
        CP_COMMIT();
    }
    CP_WAIT(STAGES - 2);
    __syncthreads();

    uint32_t af[2][4][4];
    uint32_t bf[2][4][4];

    // preload kb=0 of first stage
    {
        const uint32_t aBase = sbase + cx.aOff;
        const uint32_t bBase = sbase + cx.bOff;
        #pragma unroll
        for (int mi = 0; mi < 4; mi++)
            ldmatrix_x4(af[0][mi], aBase + (uint32_t)(mi * 16 * ROWH * 2));
        #pragma unroll
        for (int np = 0; np < 4; np++)
            ldmatrix_x4(bf[0][np], bBase + (uint32_t)(np * 16 * ROWH * 2));
    }

    for (int k = kbeg; k < kend; k++) {
        const int cur = (k - kbeg) % STAGES;
        const bool do_pref = (k + STAGES - 1 < kend);
        const int s = (k - kbeg + STAGES - 1) % STAGES;
        const size_t k0 = (size_t)(k + STAGES - 1) * TK;

        const uint32_t aBase = sbase + (uint32_t)(cur * STAGE_H) * 2 + cx.aOff;
        const uint32_t bBase = sbase + (uint32_t)(cur * STAGE_H) * 2 + cx.bOff;

        #pragma unroll
        for (int kb = 0; kb < 4; kb++) {
            const int cb = kb & 1;
            const int nb = cb ^ 1;

            if (kb < 3) {
                const uint32_t kByte = (uint32_t)((kb + 1) * 16 * 2);
                #pragma unroll
                for (int mi = 0; mi < 4; mi++)
                    ldmatrix_x4(af[nb][mi], aBase + (uint32_t)(mi * 16 * ROWH * 2) + kByte);
                #pragma unroll
                for (int np = 0; np < 4; np++)
                    ldmatrix_x4(bf[nb][np], bBase + (uint32_t)(np * 16 * ROWH * 2) + kByte);
            }

            #pragma unroll
            for (int mi = 0; mi < 4; mi++)
                #pragma unroll
                for (int np = 0; np < 4; np++) {
                    mma_f16(acc[mi][2*np][0], acc[mi][2*np][1], acc[mi][2*np][2], acc[mi][2*np][3],
                            af[cb][mi][0], af[cb][mi][1], af[cb][mi][2], af[cb][mi][3],
                            bf[cb][np][0], bf[cb][np][1]);
                    mma_f16(acc[mi][2*np+1][0], acc[mi][2*np+1][1], acc[mi][2*np+1][2], acc[mi][2*np+1][3],
                            af[cb][mi][0], af[cb][mi][1], af[cb][mi][2], af[cb][mi][3],
                            bf[cb][np][2], bf[cb][np][3]);
                }

            // spread next-stage cp.asyncs across kb steps, after this kb's MMAs
            if (do_pref) {
                #pragma unroll
                for (int i = 0; i < 4; i++) {
                    const int r = (kb & 1) * 4 + i;
                    if (kb < 2)
                        cp_async16(cx.sA_st + (uint32_t)(s * STAGE_H + r * 16 * ROWH) * 2,
                                   cx.gA + k0 + (size_t)r * 16 * N_DIM);
                    else
                        cp_async16(cx.sB_st + (uint32_t)(s * STAGE_H + r * 16 * ROWH) * 2,
                                   cx.gB + k0 + (size_t)r * 16 * N_DIM);
                }
            }
        }
        CP_COMMIT();

        CP_WAIT(STAGES - 2);
        __syncthreads();

        if (k + 1 < kend) {
            const int nxt = (k + 1 - kbeg) % STAGES;
            const uint32_t aB2 = sbase + (uint32_t)(nxt * STAGE_H) * 2 + cx.aOff;
            const uint32_t bB2 = sbase + (uint32_t)(nxt * STAGE_H) * 2 + cx.bOff;
            #pragma unroll
            for (int mi = 0; mi < 4; mi++)
                ldmatrix_x4(af[0][mi], aB2 + (uint32_t)(mi * 16 * ROWH * 2));
            #pragma unroll
            for (int np = 0; np < 4; np++)
                ldmatrix_x4(bf[0][np], bB2 + (uint32_t)(np * 16 * ROWH * 2));
        }
    }
}

__device__ __forceinline__ void make_ctx(GemmCtx& cx, uint32_t sbase, int tid,
                                         int b, int d0, int n0, int wm, int wn)
{
    const int lane = tid & 31;
    const int crow = tid >> 3;
    const int cc   = tid & 7;
    cx.sbase = sbase;
    cx.gA = g_xh   + ((size_t)b * D_DIM + d0 + crow) * N_DIM + cc * 8;
    cx.gB = g_adjh + ((size_t)b * N_DIM + n0 + crow) * N_DIM + cc * 8;
    cx.sA_st = sbase + (uint32_t)(crow * ROWH + cc * 8) * 2;
    cx.sB_st = cx.sA_st + TILE_H * 2;
    cx.aOff = (uint32_t)(((wm + (lane & 15)) * ROWH + (lane >> 4) * 8) * 2);
    cx.bOff = (uint32_t)(((wn + ((lane >> 4) << 3) + (lane & 7)) * ROWH
                          + ((lane >> 3) & 1) * 8) * 2) + TILE_H * 2;
}

// ---------------- per-half GEMM kernel: 1520 main tiles + 128 rem CTAs (last, fused reduce) ----------------
__global__ void __launch_bounds__(128, 2)
gcn_f16_mma_kernel(float* __restrict__ out, int batch)
{
    extern __shared__ __half smem[];
    __shared__ int s_last;
    const uint32_t sbase = smem_u32(smem);
    const int tid = threadIdx.x;
    const int wid = tid >> 5;
    const int lane = tid & 31;
    const int wm = (wid & 1) * 64;
    const int wn = (wid >> 1) * 64;

    const int bx = blockIdx.x;
    const bool is_rem = (bx >= MAIN_H);

    int tile, kbeg, kend;
    if (is_rem) {
        const int rix = bx - MAIN_H;         // 0..127
        tile = MAIN_H + (rix >> 3);          // 1520..1535
        const int kp = rix & 7;
        kbeg = kp * NK_PART;
        kend = kbeg + NK_PART;
    } else {
        tile = bx;                           // 0..1519
        kbeg = 0;
        kend = NK;
    }

    const int mt = tile % MT;                // m-fast raster within the half
    const int nt = tile / MT;
    const int d0 = mt * TM;
    const int n0 = nt * TN;

    GemmCtx cx;
    make_ctx(cx, sbase, tid, batch, d0, n0, wm, wn);

    float acc[4][8][4];
    #pragma unroll
    for (int i = 0; i < 4; i++)
        #pragma unroll
        for (int j = 0; j < 8; j++)
            #pragma unroll
            for (int r = 0; r < 4; r++) acc[i][j][r] = 0.0f;

    gemm_tile(cx, kbeg, kend, acc);

    if (is_rem) {
        const int rix = bx - MAIN_H;
        const int t  = rix >> 3;             // 0..15
        float* pb = g_part + (size_t)rix * (TM * TN);
        #pragma unroll
        for (int mi = 0; mi < 4; mi++) {
            const int r0 = wm + mi * 16 + (lane >> 2);
            #pragma unroll
            for (int ni = 0; ni < 8; ni++) {
                const int c = wn + ni * 8 + (lane & 3) * 2;
                float2 v0 = make_float2(acc[mi][ni][0], acc[mi][ni][1]);
                float2 v1 = make_float2(acc[mi][ni][2], acc[mi][ni][3]);
                *reinterpret_cast<float2*>(pb + (size_t)r0 * TN + c) = v0;
                *reinterpret_cast<float2*>(pb + (size_t)(r0 + 8) * TN + c) = v1;
            }
        }

        // threadfence-reduction: 8th arriver for this tile sums all partials into out
        __threadfence();
        __syncthreads();
        if (tid == 0)
            s_last = (atomicAdd(&g_cnt[batch * REM_H + t], 1) == KSPLIT - 1);
        __syncthreads();

        if (s_last) {
            const float* base = g_part + (size_t)t * KSPLIT * (TM * TN);
            float* ob = out + ((size_t)batch * D_DIM + d0) * N_DIM + n0;
            for (int e4 = tid; e4 < TM * TN / 4; e4 += 128) {
                const int e = e4 * 4;
                float4 sv = *reinterpret_cast<const float4*>(base + e);
                #pragma unroll
                for (int p = 1; p < KSPLIT; p++) {
                    float4 v = *reinterpret_cast<const float4*>(base + (size_t)p * (TM * TN) + e);
                    sv.x += v.x; sv.y += v.y; sv.z += v.z; sv.w += v.w;
                }
                const int row = e / TN;
                const int col = e % TN;
                *reinterpret_cast<float4*>(ob + (size_t)row * N_DIM + col) = sv;
            }
        }
    } else {
        float* ob = out + ((size_t)batch * D_DIM) * N_DIM;
        #pragma unroll
        for (int mi = 0; mi < 4; mi++) {
            const int r0 = d0 + wm + mi * 16 + (lane >> 2);
            #pragma unroll
            for (int ni = 0; ni < 8; ni++) {
                const int c = n0 + wn + ni * 8 + (lane & 3) * 2;
                float2 v0 = make_float2(acc[mi][ni][0], acc[mi][ni][1]);
                float2 v1 = make_float2(acc[mi][ni][2], acc[mi][ni][3]);
                *reinterpret_cast<float2*>(ob + (size_t)r0 * N_DIM + c) = v0;
                *reinterpret_cast<float2*>(ob + (size_t)(r0 + 8) * N_DIM + c) = v1;
            }
        }
    }
}

// ---------------- host launch: fork-join graph, cvt_b1 overlaps GEMM_b0 ----------------
extern "C" void kernel_launch(void* const* d_in, const int* in_sizes, int n_in,
                              void* d_out, int out_size)
{
    const float* x;
    const float* adj;
    if (in_sizes[0] == B_DIM * D_DIM * N_DIM) {
        x = (const float*)d_in[0]; adj = (const float*)d_in[1];
    } else {
        x = (const float*)d_in[1]; adj = (const float*)d_in[0];
    }

    __half* xh;
    __half* adjh;
    cudaGetSymbolAddress((void**)&xh, g_xh);
    cudaGetSymbolAddress((void**)&adjh, g_adjh);

    // side stream + events: created once on the first (non-captured) correctness call,
    // reused identically in every capture -> captured graph is deterministic.
    static cudaStream_t s2 = nullptr;
    static cudaEvent_t evFork = nullptr, evJoin = nullptr;
    if (s2 == nullptr) {
        cudaStreamCreateWithFlags(&s2, cudaStreamNonBlocking);
        cudaEventCreateWithFlags(&evFork, cudaEventDisableTiming);
        cudaEventCreateWithFlags(&evJoin, cudaEventDisableTiming);
        cudaFuncSetAttribute(gcn_f16_mma_kernel, cudaFuncAttributeMaxDynamicSharedMemorySize, SMEM_BYTES);
    }
    // attribute is sticky; set again defensively on every call (idempotent, capture-legal)
    cudaFuncSetAttribute(gcn_f16_mma_kernel, cudaFuncAttributeMaxDynamicSharedMemorySize, SMEM_BYTES);

    const size_t nxh = (size_t)D_DIM * N_DIM;   // per-batch x elems
    const size_t nah = (size_t)N_DIM * N_DIM;   // per-batch adj elems

    // batch 0 conversion (also resets rem counters for both halves)
    cvt_f2h_half_kernel<<<CVT_BLOCKS, CVT_THREADS>>>(x, xh, nxh, adj, adjh, nah, 1);

    // fork: cvt for batch 1 runs concurrently with GEMM for batch 0
    cudaEventRecord(evFork, 0);
    cudaStreamWaitEvent(s2, evFork, 0);
    cvt_f2h_half_kernel<<<CVT_BLOCKS, CVT_THREADS, 0, s2>>>(x + nxh, xh + nxh, nxh,
                                                            adj + nah, adjh + nah, nah, 0);
    gcn_f16_mma_kernel<<<GRID_H, 128, SMEM_BYTES>>>((float*)d_out, 0);

    // join: GEMM for batch 1 needs both GEMM_b0 (stream order) and cvt_b1
    cudaEventRecord(evJoin, s2);
    cudaStreamWaitEvent(0, evJoin, 0);
    gcn_f16_mma_kernel<<<GRID_H, 128, SMEM_BYTES>>>((float*)d_out, 1);
}

// round 17
// speedup vs baseline: 1.0066x; 1.0066x over previous
#include <cuda_runtime.h>
#include <cuda_fp16.h>
#include <cstdint>

// ---------------- problem constants ----------------
#define D_DIM 3072
#define N_DIM 8192
#define B_DIM 2

#define TM 128            // CTA M tile (d)
#define TN 128            // CTA N tile (n)
#define TK 64             // K tile (halves) = 128B per row
#define STAGES 3
#define NK (N_DIM / TK)   // 128 k iterations
#define MT (D_DIM / TM)   // 24
#define NT (N_DIM / TN)   // 64

// per-batch-half tiling: 1536 tiles = 1520 main (5 exact waves of 304) + 16 split-K tiles
#define TILES_H     (MT * NT)          // 1536
#define MAIN_H      1520
#define REM_H       (TILES_H - MAIN_H) // 16
#define KSPLIT      8
#define NK_PART     (NK / KSPLIT)      // 16
#define REM_CTAS_H  (REM_H * KSPLIT)   // 128
#define GRID_H      (MAIN_H + REM_CTAS_H) // 1648

#define ROWH 72                           // padded row (halves): conflict-free ldmatrix
#define TILE_H (128 * ROWH)               // 9216 halves per 128-row tile
#define STAGE_H (2 * TILE_H)              // A + B per stage = 36864 B
#define SMEM_BYTES (STAGES * STAGE_H * 2) // 110592 B -> 2 CTAs/SM

// cvt per-half grid: blocks < CVT_X_BLOCKS sweep x-half, rest sweep adj-half
#define CVT_BLOCKS   6080
#define CVT_X_BLOCKS 1664
#define CVT_THREADS  128

// fp16 scratch copies of the inputs (zero-init .bss; no runtime allocation)
__device__ __half g_xh[(size_t)B_DIM * D_DIM * N_DIM];
__device__ __half g_adjh[(size_t)B_DIM * N_DIM * N_DIM];
// split-K partials + counters PER BATCH (both halves may execute concurrently)
__device__ float g_part[(size_t)B_DIM * REM_H * KSPLIT * TM * TN];
__device__ int   g_cnt[B_DIM * REM_H];

// ---------------- PTX helpers ----------------
__device__ __forceinline__ uint32_t smem_u32(const void* p) {
    uint32_t a;
    asm("{ .reg .u64 t; cvta.to.shared.u64 t, %1; cvt.u32.u64 %0, t; }" : "=r"(a) : "l"(p));
    return a;
}
__device__ __forceinline__ void cp_async16(uint32_t saddr, const void* gaddr) {
    asm volatile("cp.async.cg.shared.global [%0], [%1], 16;" :: "r"(saddr), "l"(gaddr) : "memory");
}
#define CP_COMMIT() asm volatile("cp.async.commit_group;" ::: "memory")
#define CP_WAIT(n)  asm volatile("cp.async.wait_group %0;" :: "n"(n) : "memory")

__device__ __forceinline__ void ldmatrix_x4(uint32_t* r, uint32_t addr) {
    asm volatile("ldmatrix.sync.aligned.m8n8.x4.shared.b16 {%0,%1,%2,%3}, [%4];"
        : "=r"(r[0]), "=r"(r[1]), "=r"(r[2]), "=r"(r[3]) : "r"(addr));
}
__device__ __forceinline__ void mma_f16(float& c0, float& c1, float& c2, float& c3,
                                        uint32_t a0, uint32_t a1, uint32_t a2, uint32_t a3,
                                        uint32_t b0, uint32_t b1) {
    asm volatile(
        "mma.sync.aligned.m16n8k16.row.col.f32.f16.f16.f32 "
        "{%0,%1,%2,%3}, {%4,%5,%6,%7}, {%8,%9}, {%0,%1,%2,%3};"
        : "+f"(c0), "+f"(c1), "+f"(c2), "+f"(c3)
        : "r"(a0), "r"(a1), "r"(a2), "r"(a3), "r"(b0), "r"(b1));
}
__device__ __forceinline__ uint32_t pack_h2(float lo, float hi) {
    uint32_t u;
    asm("cvt.rn.f16x2.f32 %0, %1, %2;" : "=r"(u) : "f"(hi), "f"(lo));
    return u;
}

// ---------------- prepass: fp32 -> fp16 for ONE batch half ----------------
__global__ void __launch_bounds__(CVT_THREADS)
cvt_f2h_half_kernel(const float* __restrict__ x, __half* __restrict__ xh, size_t nx,
                    const float* __restrict__ adj, __half* __restrict__ adjh, size_t na,
                    int do_reset)
{
    // cvt_b0 resets BOTH halves' rem counters; the fork edge orders this before both GEMMs
    if (do_reset && blockIdx.x == 0 && threadIdx.x < B_DIM * REM_H)
        g_cnt[threadIdx.x] = 0;

    const float* src;
    __half* dst;
    size_t n8, idx, stride;
    if (blockIdx.x < CVT_X_BLOCKS) {
        src = x;   dst = xh;   n8 = nx / 8;
        idx = (size_t)blockIdx.x * CVT_THREADS + threadIdx.x;
        stride = (size_t)CVT_X_BLOCKS * CVT_THREADS;
    } else {
        src = adj; dst = adjh; n8 = na / 8;
        idx = (size_t)(blockIdx.x - CVT_X_BLOCKS) * CVT_THREADS + threadIdx.x;
        stride = (size_t)(CVT_BLOCKS - CVT_X_BLOCKS) * CVT_THREADS;
    }
    for (; idx < n8; idx += stride) {
        const size_t i = idx * 8;
        float4 f0 = *reinterpret_cast<const float4*>(src + i);
        float4 f1 = *reinterpret_cast<const float4*>(src + i + 4);
        uint4 v;
        v.x = pack_h2(f0.x, f0.y);
        v.y = pack_h2(f0.z, f0.w);
        v.z = pack_h2(f1.x, f1.y);
        v.w = pack_h2(f1.z, f1.w);
        *reinterpret_cast<uint4*>(dst + i) = v;
    }
}

// ---------------- shared GEMM body (proven R10/R13 version) ----------------
struct GemmCtx {
    uint32_t sA_st, sB_st, aOff, bOff, sbase;
    const __half* gA;
    const __half* gB;
};

__device__ __forceinline__ void gemm_tile(const GemmCtx& cx, int kbeg, int kend,
                                          float (&acc)[4][8][4])
{
    const uint32_t sbase = cx.sbase;
    // prologue
    #pragma unroll
    for (int s = 0; s < STAGES - 1; s++) {
        const size_t k0 = (size_t)(kbeg + s) * TK;
        #pragma unroll
        for (int i = 0; i < 8; i++) {
            cp_async16(cx.sA_st + (uint32_t)(s * STAGE_H + i * 16 * ROWH) * 2, cx.gA + k0 + (size_t)i * 16 * N_DIM);
            cp_async16(cx.sB_st + (uint32_t)(s * STAGE_H + i * 16 * ROWH) * 2, cx.gB + k0 + (size_t)i * 16 * N_DIM);
        }
        CP_COMMIT();
    }
    CP_WAIT(STAGES - 2);
    __syncthreads();

    uint32_t af[2][4][4];
    uint32_t bf[2][4][4];

    // preload kb=0 of first stage
    {
        const uint32_t aBase = sbase + cx.aOff;
        const uint32_t bBase = sbase + cx.bOff;
        #pragma unroll
        for (int mi = 0; mi < 4; mi++)
            ldmatrix_x4(af[0][mi], aBase + (uint32_t)(mi * 16 * ROWH * 2));
        #pragma unroll
        for (int np = 0; np < 4; np++)
            ldmatrix_x4(bf[0][np], bBase + (uint32_t)(np * 16 * ROWH * 2));
    }

    for (int k = kbeg; k < kend; k++) {
        const int cur = (k - kbeg) % STAGES;
        const bool do_pref = (k + STAGES - 1 < kend);
        const int s = (k - kbeg + STAGES - 1) % STAGES;
        const size_t k0 = (size_t)(k + STAGES - 1) * TK;

        const uint32_t aBase = sbase + (uint32_t)(cur * STAGE_H) * 2 + cx.aOff;
        const uint32_t bBase = sbase + (uint32_t)(cur * STAGE_H) * 2 + cx.bOff;

        #pragma unroll
        for (int kb = 0; kb < 4; kb++) {
            const int cb = kb & 1;
            const int nb = cb ^ 1;

            if (kb < 3) {
                const uint32_t kByte = (uint32_t)((kb + 1) * 16 * 2);
                #pragma unroll
                for (int mi = 0; mi < 4; mi++)
                    ldmatrix_x4(af[nb][mi], aBase + (uint32_t)(mi * 16 * ROWH * 2) + kByte);
                #pragma unroll
                for (int np = 0; np < 4; np++)
                    ldmatrix_x4(bf[nb][np], bBase + (uint32_t)(np * 16 * ROWH * 2) + kByte);
            }

            #pragma unroll
            for (int mi = 0; mi < 4; mi++)
                #pragma unroll
                for (int np = 0; np < 4; np++) {
                    mma_f16(acc[mi][2*np][0], acc[mi][2*np][1], acc[mi][2*np][2], acc[mi][2*np][3],
                            af[cb][mi][0], af[cb][mi][1], af[cb][mi][2], af[cb][mi][3],
                            bf[cb][np][0], bf[cb][np][1]);
                    mma_f16(acc[mi][2*np+1][0], acc[mi][2*np+1][1], acc[mi][2*np+1][2], acc[mi][2*np+1][3],
                            af[cb][mi][0], af[cb][mi][1], af[cb][mi][2], af[cb][mi][3],
                            bf[cb][np][2], bf[cb][np][3]);
                }

            // spread next-stage cp.asyncs across kb steps, after this kb's MMAs
            if (do_pref) {
                #pragma unroll
                for (int i = 0; i < 4; i++) {
                    const int r = (kb & 1) * 4 + i;
                    if (kb < 2)
                        cp_async16(cx.sA_st + (uint32_t)(s * STAGE_H + r * 16 * ROWH) * 2,
                                   cx.gA + k0 + (size_t)r * 16 * N_DIM);
                    else
                        cp_async16(cx.sB_st + (uint32_t)(s * STAGE_H + r * 16 * ROWH) * 2,
                                   cx.gB + k0 + (size_t)r * 16 * N_DIM);
                }
            }
        }
        CP_COMMIT();

        CP_WAIT(STAGES - 2);
        __syncthreads();

        if (k + 1 < kend) {
            const int nxt = (k + 1 - kbeg) % STAGES;
            const uint32_t aB2 = sbase + (uint32_t)(nxt * STAGE_H) * 2 + cx.aOff;
            const uint32_t bB2 = sbase + (uint32_t)(nxt * STAGE_H) * 2 + cx.bOff;
            #pragma unroll
            for (int mi = 0; mi < 4; mi++)
                ldmatrix_x4(af[0][mi], aB2 + (uint32_t)(mi * 16 * ROWH * 2));
            #pragma unroll
            for (int np = 0; np < 4; np++)
                ldmatrix_x4(bf[0][np], bB2 + (uint32_t)(np * 16 * ROWH * 2));
        }
    }
}

__device__ __forceinline__ void make_ctx(GemmCtx& cx, uint32_t sbase, int tid,
                                         int b, int d0, int n0, int wm, int wn)
{
    const int lane = tid & 31;
    const int crow = tid >> 3;
    const int cc   = tid & 7;
    cx.sbase = sbase;
    cx.gA = g_xh   + ((size_t)b * D_DIM + d0 + crow) * N_DIM + cc * 8;
    cx.gB = g_adjh + ((size_t)b * N_DIM + n0 + crow) * N_DIM + cc * 8;
    cx.sA_st = sbase + (uint32_t)(crow * ROWH + cc * 8) * 2;
    cx.sB_st = cx.sA_st + TILE_H * 2;
    cx.aOff = (uint32_t)(((wm + (lane & 15)) * ROWH + (lane >> 4) * 8) * 2);
    cx.bOff = (uint32_t)(((wn + ((lane >> 4) << 3) + (lane & 7)) * ROWH
                          + ((lane >> 3) & 1) * 8) * 2) + TILE_H * 2;
}

// ---------------- per-half GEMM kernel: 1520 main tiles + 128 rem CTAs (last, fused reduce) ----------------
__global__ void __launch_bounds__(128, 2)
gcn_f16_mma_kernel(float* __restrict__ out, int batch)
{
    extern __shared__ __half smem[];
    __shared__ int s_last;
    const uint32_t sbase = smem_u32(smem);
    const int tid = threadIdx.x;
    const int wid = tid >> 5;
    const int lane = tid & 31;
    const int wm = (wid & 1) * 64;
    const int wn = (wid >> 1) * 64;

    const int bx = blockIdx.x;
    const bool is_rem = (bx >= MAIN_H);

    int tile, kbeg, kend;
    if (is_rem) {
        const int rix = bx - MAIN_H;         // 0..127
        tile = MAIN_H + (rix >> 3);          // 1520..1535
        const int kp = rix & 7;
        kbeg = kp * NK_PART;
        kend = kbeg + NK_PART;
    } else {
        tile = bx;                           // 0..1519
        kbeg = 0;
        kend = NK;
    }

    const int mt = tile % MT;                // m-fast raster within the half
    const int nt = tile / MT;
    const int d0 = mt * TM;
    const int n0 = nt * TN;

    GemmCtx cx;
    make_ctx(cx, sbase, tid, batch, d0, n0, wm, wn);

    float acc[4][8][4];
    #pragma unroll
    for (int i = 0; i < 4; i++)
        #pragma unroll
        for (int j = 0; j < 8; j++)
            #pragma unroll
            for (int r = 0; r < 4; r++) acc[i][j][r] = 0.0f;

    gemm_tile(cx, kbeg, kend, acc);

    if (is_rem) {
        const int rix = bx - MAIN_H;
        const int t  = rix >> 3;             // 0..15
        float* pb = g_part + ((size_t)batch * REM_CTAS_H + rix) * (TM * TN);
        #pragma unroll
        for (int mi = 0; mi < 4; mi++) {
            const int r0 = wm + mi * 16 + (lane >> 2);
            #pragma unroll
            for (int ni = 0; ni < 8; ni++) {
                const int c = wn + ni * 8 + (lane & 3) * 2;
                float2 v0 = make_float2(acc[mi][ni][0], acc[mi][ni][1]);
                float2 v1 = make_float2(acc[mi][ni][2], acc[mi][ni][3]);
                *reinterpret_cast<float2*>(pb + (size_t)r0 * TN + c) = v0;
                *reinterpret_cast<float2*>(pb + (size_t)(r0 + 8) * TN + c) = v1;
            }
        }

        // threadfence-reduction: 8th arriver for this tile sums all partials into out
        __threadfence();
        __syncthreads();
        if (tid == 0)
            s_last = (atomicAdd(&g_cnt[batch * REM_H + t], 1) == KSPLIT - 1);
        __syncthreads();

        if (s_last) {
            const float* base = g_part + ((size_t)batch * REM_CTAS_H + (size_t)t * KSPLIT) * (TM * TN);
            float* ob = out + ((size_t)batch * D_DIM + d0) * N_DIM + n0;
            for (int e4 = tid; e4 < TM * TN / 4; e4 += 128) {
                const int e = e4 * 4;
                float4 sv = *reinterpret_cast<const float4*>(base + e);
                #pragma unroll
                for (int p = 1; p < KSPLIT; p++) {
                    float4 v = *reinterpret_cast<const float4*>(base + (size_t)p * (TM * TN) + e);
                    sv.x += v.x; sv.y += v.y; sv.z += v.z; sv.w += v.w;
                }
                const int row = e / TN;
                const int col = e % TN;
                *reinterpret_cast<float4*>(ob + (size_t)row * N_DIM + col) = sv;
            }
        }
    } else {
        float* ob = out + ((size_t)batch * D_DIM) * N_DIM;
        #pragma unroll
        for (int mi = 0; mi < 4; mi++) {
            const int r0 = d0 + wm + mi * 16 + (lane >> 2);
            #pragma unroll
            for (int ni = 0; ni < 8; ni++) {
                const int c = n0 + wn + ni * 8 + (lane & 3) * 2;
                float2 v0 = make_float2(acc[mi][ni][0], acc[mi][ni][1]);
                float2 v1 = make_float2(acc[mi][ni][2], acc[mi][ni][3]);
                *reinterpret_cast<float2*>(ob + (size_t)r0 * N_DIM + c) = v0;
                *reinterpret_cast<float2*>(ob + (size_t)(r0 + 8) * N_DIM + c) = v1;
            }
        }
    }
}

// ---------------- host launch: true dependency DAG ----------------
// origin: cvt_b0 -> GEMM_b0
// s2:     (after cvt_b0) cvt_b1 -> GEMM_b1
// join s2 into origin at the end. GEMM_b1 does NOT depend on GEMM_b0.
extern "C" void kernel_launch(void* const* d_in, const int* in_sizes, int n_in,
                              void* d_out, int out_size)
{
    const float* x;
    const float* adj;
    if (in_sizes[0] == B_DIM * D_DIM * N_DIM) {
        x = (const float*)d_in[0]; adj = (const float*)d_in[1];
    } else {
        x = (const float*)d_in[1]; adj = (const float*)d_in[0];
    }

    __half* xh;
    __half* adjh;
    cudaGetSymbolAddress((void**)&xh, g_xh);
    cudaGetSymbolAddress((void**)&adjh, g_adjh);

    static cudaStream_t s2 = nullptr;
    static cudaEvent_t evFork = nullptr, evJoin = nullptr;
    if (s2 == nullptr) {
        cudaStreamCreateWithFlags(&s2, cudaStreamNonBlocking);
        cudaEventCreateWithFlags(&evFork, cudaEventDisableTiming);
        cudaEventCreateWithFlags(&evJoin, cudaEventDisableTiming);
    }
    cudaFuncSetAttribute(gcn_f16_mma_kernel, cudaFuncAttributeMaxDynamicSharedMemorySize, SMEM_BYTES);

    const size_t nxh = (size_t)D_DIM * N_DIM;   // per-batch x elems
    const size_t nah = (size_t)N_DIM * N_DIM;   // per-batch adj elems

    // batch-0 conversion (also resets both halves' rem counters)
    cvt_f2h_half_kernel<<<CVT_BLOCKS, CVT_THREADS>>>(x, xh, nxh, adj, adjh, nah, 1);

    // fork: batch-1 chain on s2 (depends only on cvt_b0 via the event)
    cudaEventRecord(evFork, 0);
    cudaStreamWaitEvent(s2, evFork, 0);
    cvt_f2h_half_kernel<<<CVT_BLOCKS, CVT_THREADS, 0, s2>>>(x + nxh, xh + nxh, nxh,
                                                            adj + nah, adjh + nah, nah, 0);
    gcn_f16_mma_kernel<<<GRID_H, 128, SMEM_BYTES, s2>>>((float*)d_out, 1);

    // batch-0 GEMM on the origin stream, concurrent with the s2 chain
    gcn_f16_mma_kernel<<<GRID_H, 128, SMEM_BYTES>>>((float*)d_out, 0);

    // join
    cudaEventRecord(evJoin, s2);
    cudaStreamWaitEvent(0, evJoin, 0);
}